// round 13
// baseline (speedup 1.0000x reference)
#include <cuda_runtime.h>

#define LQ 4096
#define SK 4096
#define NH_TOT 64      // N*H = 8*8
#define DD 64
#define MM 64
#define S1_CHUNKS 32
#define S1_ROWS (SK / S1_CHUNKS)   // 128
#define LTILE 64

typedef unsigned long long ull;

// Scratch (__device__ globals; no allocation allowed)
__device__ float g_KVp[S1_CHUNKS * NH_TOT * DD * MM];   // per-chunk partial KV
__device__ float g_Ksp[S1_CHUNKS * NH_TOT * DD];        // per-chunk partial Ksum
__device__ float g_KV [NH_TOT * DD * MM];
__device__ float g_Ksum[NH_TOT * DD];

__device__ __forceinline__ float phi(float x) {         // elu(x)+1
    return x > 0.f ? x + 1.f : __expf(x);
}
__device__ __forceinline__ ull pack2(float lo, float hi) {
    ull r; asm("mov.b64 %0, {%1, %2};" : "=l"(r) : "f"(lo), "f"(hi)); return r;
}
__device__ __forceinline__ void ffma2(ull &d, ull a, ull b) {
    asm("fma.rn.f32x2 %0, %1, %2, %0;" : "+l"(d) : "l"(a), "l"(b));
}
__device__ __forceinline__ ull mul2(ull a, ull b) {
    ull d; asm("mul.rn.f32x2 %0, %1, %2;" : "=l"(d) : "l"(a), "l"(b)); return d;
}

union F4U { float4 f; ull u[2]; float s[4]; };

// ───────────────────────── Stage 1 ─────────────────────────
// grid (64 nh, 32 chunks), 128 threads, per-thread tile 4d x 8m.
// Per inner step: 3 LDS.128 + 4 packs + 16 ffma2 (L1TEX per FMA cut ~40%).
__global__ __launch_bounds__(128) void stage1_kernel(
    const float* __restrict__ Kg, const float* __restrict__ Vg,
    const float* __restrict__ maskg)
{
    const int nh = blockIdx.x, sc = blockIdx.y;
    const int n = nh >> 3, h = nh & 7;
    const int tid = threadIdx.x;
    const int td = tid >> 3;      // d tile: 4*td..+3   (4 distinct per warp)
    const int tm = tid & 7;       // m tile: 8*tm..+7

    __shared__ __align__(16) float ks[16][DD];
    __shared__ __align__(16) float vs[16][MM];

    ull acc[4][4];
    #pragma unroll
    for (int i = 0; i < 4; i++)
        #pragma unroll
        for (int j = 0; j < 4; j++) acc[i][j] = 0ull;
    float ksum[4] = {0.f, 0.f, 0.f, 0.f};

    const int s0 = sc * S1_ROWS;
    const int lr = tid >> 3, lc = tid & 7;   // loader: row 0..15, float4 cols lc, lc+8

    // Prefetch batch 0 into registers
    F4U kra, krb, vra, vrb; float mreg;
    {
        const int s = s0 + lr;
        const int base = ((n * SK + s) * 8 + h) * DD;
        kra.f = ((const float4*)(Kg + base))[lc];
        krb.f = ((const float4*)(Kg + base))[lc + 8];
        vra.f = ((const float4*)(Vg + base))[lc];
        vrb.f = ((const float4*)(Vg + base))[lc + 8];
        mreg = maskg[n * SK + s];
    }

    #pragma unroll 1
    for (int b = 0; b < S1_ROWS / 16; b++) {
        if (b) __syncthreads();
        F4U kw = kra;
        kw.s[0] = phi(kw.s[0]) * mreg; kw.s[1] = phi(kw.s[1]) * mreg;
        kw.s[2] = phi(kw.s[2]) * mreg; kw.s[3] = phi(kw.s[3]) * mreg;
        ((float4*)&ks[lr][0])[lc] = kw.f;
        kw = krb;
        kw.s[0] = phi(kw.s[0]) * mreg; kw.s[1] = phi(kw.s[1]) * mreg;
        kw.s[2] = phi(kw.s[2]) * mreg; kw.s[3] = phi(kw.s[3]) * mreg;
        ((float4*)&ks[lr][0])[lc + 8] = kw.f;
        ((float4*)&vs[lr][0])[lc]     = vra.f;
        ((float4*)&vs[lr][0])[lc + 8] = vrb.f;
        __syncthreads();
        // Prefetch next batch while computing
        if (b + 1 < S1_ROWS / 16) {
            const int s = s0 + (b + 1) * 16 + lr;
            const int base = ((n * SK + s) * 8 + h) * DD;
            kra.f = ((const float4*)(Kg + base))[lc];
            krb.f = ((const float4*)(Kg + base))[lc + 8];
            vra.f = ((const float4*)(Vg + base))[lc];
            vrb.f = ((const float4*)(Vg + base))[lc + 8];
            mreg = maskg[n * SK + s];
        }
        #pragma unroll
        for (int r = 0; r < 16; r++) {
            F4U k4, v0, v1;
            k4.f = ((const float4*)&ks[r][0])[td];
            v0.f = ((const float4*)&vs[r][0])[2 * tm];
            v1.f = ((const float4*)&vs[r][0])[2 * tm + 1];
            #pragma unroll
            for (int i = 0; i < 4; i++) {
                const ull kd = pack2(k4.s[i], k4.s[i]);
                ffma2(acc[i][0], kd, v0.u[0]);
                ffma2(acc[i][1], kd, v0.u[1]);
                ffma2(acc[i][2], kd, v1.u[0]);
                ffma2(acc[i][3], kd, v1.u[1]);
            }
            if (tm == 0) {
                #pragma unroll
                for (int i = 0; i < 4; i++) ksum[i] += k4.s[i];
            }
        }
    }

    float* dst = g_KVp + ((sc * NH_TOT + nh) * DD + 4 * td) * MM + 8 * tm;
    #pragma unroll
    for (int i = 0; i < 4; i++) {
        F4U lo, hi;
        lo.u[0] = acc[i][0]; lo.u[1] = acc[i][1];
        hi.u[0] = acc[i][2]; hi.u[1] = acc[i][3];
        *(float4*)(dst + i * MM)     = lo.f;
        *(float4*)(dst + i * MM + 4) = hi.f;
    }
    if (tm == 0) {
        float* kd = g_Ksp + (sc * NH_TOT + nh) * DD + 4 * td;
        #pragma unroll
        for (int i = 0; i < 4; i++) kd[i] = ksum[i];
    }
}

// ───────────────────────── Reduce partials ─────────────────────────
__global__ __launch_bounds__(256) void reduce_kernel() {
    const int idx = blockIdx.x * 256 + threadIdx.x;
    const int KV4 = NH_TOT * DD * MM / 4;    // 65536
    const int KS4 = NH_TOT * DD / 4;         // 1024
    if (idx < KV4) {
        float4 s = make_float4(0.f, 0.f, 0.f, 0.f);
        #pragma unroll 8
        for (int c = 0; c < S1_CHUNKS; c++) {
            float4 p = ((const float4*)g_KVp)[c * KV4 + idx];
            s.x += p.x; s.y += p.y; s.z += p.z; s.w += p.w;
        }
        ((float4*)g_KV)[idx] = s;
    } else if (idx < KV4 + KS4) {
        const int j = idx - KV4;
        float4 s = make_float4(0.f, 0.f, 0.f, 0.f);
        #pragma unroll 8
        for (int c = 0; c < S1_CHUNKS; c++) {
            float4 p = ((const float4*)g_Ksp)[c * KS4 + j];
            s.x += p.x; s.y += p.y; s.z += p.z; s.w += p.w;
        }
        ((float4*)g_Ksum)[j] = s;
    }
}

// ───────────────────────── Stage 2 ─────────────────────────
// grid (64 l-tiles, 64 nh), 128 threads, per-thread tile 4l x 8m.
// Q row-major [l][68] (contiguous float4 STS; stride 68 -> conflict-free
// 4-row reads). Per d-block of 4: 12 LDS.128 + 16 packs + 64 ffma2.
__global__ __launch_bounds__(128) void stage2_kernel(
    const float* __restrict__ Qg, float* __restrict__ Outg)
{
    const int nh = blockIdx.y;
    const int n = nh >> 3, h = nh & 7;
    const int l0 = blockIdx.x * LTILE;
    const int tid = threadIdx.x;
    const int tl = tid >> 3;      // l tile: 4*tl..+3
    const int tm = tid & 7;       // m tile: 8*tm..+7

    __shared__ __align__(16) float Qs[LTILE][68];   // [l][d] row-major, padded
    __shared__ __align__(16) float KVs[DD][MM];
    __shared__ float ksums[DD];
    __shared__ float zs[LTILE];

    // Load Q tile with phi applied: float4 LDG + contiguous float4 STS
    #pragma unroll
    for (int u = 0; u < 8; u++) {
        const int i4 = tid + 128 * u;        // 0..1023 float4s
        const int l = i4 >> 4, c = i4 & 15;
        F4U q4; q4.f = *((const float4*)(Qg + ((n * LQ + l0 + l) * 8 + h) * DD) + c);
        q4.s[0] = phi(q4.s[0]); q4.s[1] = phi(q4.s[1]);
        q4.s[2] = phi(q4.s[2]); q4.s[3] = phi(q4.s[3]);
        *(float4*)&Qs[l][4 * c] = q4.f;
    }
    // Load KV (L2-resident) and Ksum
    #pragma unroll
    for (int u = 0; u < 8; u++)
        ((float4*)KVs)[tid + 128 * u] = ((const float4*)(g_KV + nh * DD * MM))[tid + 128 * u];
    if (tid < DD) ksums[tid] = g_Ksum[nh * DD + tid];
    __syncthreads();

    // z[l] = 1/(phi(q)[l] . Ksum + eps)
    if (tid < LTILE) {
        float a = 0.f;
        #pragma unroll
        for (int c = 0; c < 16; c++) {
            F4U q4; q4.f = *(const float4*)&Qs[tid][4 * c];
            F4U s4; s4.f = *(const float4*)&ksums[4 * c];
            a = fmaf(q4.s[0], s4.s[0], a); a = fmaf(q4.s[1], s4.s[1], a);
            a = fmaf(q4.s[2], s4.s[2], a); a = fmaf(q4.s[3], s4.s[3], a);
        }
        zs[tid] = 1.f / (a + 1e-6f);
    }
    __syncthreads();

    ull acc[4][4];
    #pragma unroll
    for (int i = 0; i < 4; i++)
        #pragma unroll
        for (int j = 0; j < 4; j++) acc[i][j] = 0ull;

    #pragma unroll 2
    for (int d0 = 0; d0 < DD; d0 += 4) {
        F4U q4[4];
        #pragma unroll
        for (int i = 0; i < 4; i++)
            q4[i].f = *(const float4*)&Qs[4 * tl + i][d0];
        #pragma unroll
        for (int j = 0; j < 4; j++) {
            F4U ka, kb;
            ka.f = ((const float4*)&KVs[d0 + j][0])[2 * tm];
            kb.f = ((const float4*)&KVs[d0 + j][0])[2 * tm + 1];
            #pragma unroll
            for (int i = 0; i < 4; i++) {
                const ull qq = pack2(q4[i].s[j], q4[i].s[j]);
                ffma2(acc[i][0], qq, ka.u[0]);
                ffma2(acc[i][1], qq, ka.u[1]);
                ffma2(acc[i][2], qq, kb.u[0]);
                ffma2(acc[i][3], qq, kb.u[1]);
            }
        }
    }

    #pragma unroll
    for (int i = 0; i < 4; i++) {
        const int l = l0 + 4 * tl + i;
        const float z = zs[4 * tl + i];
        const ull zz = pack2(z, z);
        F4U lo, hi;
        lo.u[0] = mul2(acc[i][0], zz); lo.u[1] = mul2(acc[i][1], zz);
        hi.u[0] = mul2(acc[i][2], zz); hi.u[1] = mul2(acc[i][3], zz);
        float* o = Outg + ((n * LQ + l) * 8 + h) * MM + 8 * tm;
        *(float4*)o       = lo.f;
        *(float4*)(o + 4) = hi.f;
    }
}

extern "C" void kernel_launch(void* const* d_in, const int* in_sizes, int n_in,
                              void* d_out, int out_size)
{
    const float* Q    = (const float*)d_in[0];
    const float* K    = (const float*)d_in[1];
    const float* V    = (const float*)d_in[2];
    const float* mask = (const float*)d_in[3];
    float* Out = (float*)d_out;

    stage1_kernel<<<dim3(NH_TOT, S1_CHUNKS), 128>>>(K, V, mask);
    reduce_kernel<<<260, 256>>>();
    stage2_kernel<<<dim3(LQ / LTILE, NH_TOT), 128>>>(Q, Out);
}